// round 12
// baseline (speedup 1.0000x reference)
#include <cuda_runtime.h>
#include <cuda_fp16.h>
#include <cstdint>

// ---------------------------------------------------------------------------
// QWenAttention: B=1, S=2048, H=2048, NH=16, HD=128
//   qkv = hidden @ w_qkv + b_qkv; rope(q,k); ctx = causal_attn(q,k,v);
//   out = ctx @ w_proj
// fp16 mma.sync m16n8k16 (fp32 accum); ldmatrix fragments; GEMM 128x256
// 3-stage cp.async (dynamic smem) with RoPE fused into the QKV epilogue
// (in registers, fp32, pre-rounding); flash unchanged from round 10.
// ---------------------------------------------------------------------------

#define S_LEN 2048
#define HID   2048
#define NHEAD 16
#define HDIM  128
#define QKV_N 6144

__device__ __align__(16) __half g_qkv_h[S_LEN * QKV_N];
__device__ __align__(16) __half g_ctx_h[S_LEN * HID];
__device__ __align__(16) __half g_hid_h[S_LEN * HID];
__device__ __align__(16) __half g_w1t_h[QKV_N * HID];   // [N,K]
__device__ __align__(16) __half g_w2t_h[HID * HID];     // [N,K]
__device__ __align__(16) float  g_cos[S_LEN * 64];
__device__ __align__(16) float  g_sin[S_LEN * 64];

// ---------------------------------------------------------------------------
// helpers
// ---------------------------------------------------------------------------
__device__ __forceinline__ void mma_fp16(float* c, const uint32_t* a, const uint32_t* b) {
    asm volatile(
        "mma.sync.aligned.m16n8k16.row.col.f32.f16.f16.f32 "
        "{%0,%1,%2,%3}, {%4,%5,%6,%7}, {%8,%9}, {%0,%1,%2,%3};\n"
        : "+f"(c[0]), "+f"(c[1]), "+f"(c[2]), "+f"(c[3])
        : "r"(a[0]), "r"(a[1]), "r"(a[2]), "r"(a[3]), "r"(b[0]), "r"(b[1]));
}
__device__ __forceinline__ void ldsm_x4(uint32_t* r, uint32_t addr) {
    asm volatile("ldmatrix.sync.aligned.m8n8.x4.shared.b16 {%0,%1,%2,%3}, [%4];"
        : "=r"(r[0]), "=r"(r[1]), "=r"(r[2]), "=r"(r[3]) : "r"(addr));
}
__device__ __forceinline__ void ldsm_x4_t(uint32_t* r, uint32_t addr) {
    asm volatile("ldmatrix.sync.aligned.m8n8.x4.trans.shared.b16 {%0,%1,%2,%3}, [%4];"
        : "=r"(r[0]), "=r"(r[1]), "=r"(r[2]), "=r"(r[3]) : "r"(addr));
}
__device__ __forceinline__ void cpa16u(uint32_t s, const void* g) {
    asm volatile("cp.async.cg.shared.global [%0], [%1], 16;\n" :: "r"(s), "l"(g));
}
__device__ __forceinline__ uint32_t smem_u32(const void* p) {
    return (uint32_t)__cvta_generic_to_shared(p);
}
__device__ __forceinline__ uint32_t pack_h2(float lo, float hi) {
    __half2 h = __floats2half2_rn(lo, hi);
    return *(uint32_t*)&h;
}

// ---------------------------------------------------------------------------
// prep kernels
// ---------------------------------------------------------------------------
__global__ void convert_half_kernel(const float* __restrict__ in,
                                    __half* __restrict__ out, int n4)
{
    int i = blockIdx.x * blockDim.x + threadIdx.x;
    if (i >= n4) return;
    float4 v = ((const float4*)in)[i];
    ((__half2*)out)[i * 2]     = __floats2half2_rn(v.x, v.y);
    ((__half2*)out)[i * 2 + 1] = __floats2half2_rn(v.z, v.w);
}

__global__ void transpose_half_kernel(const float* __restrict__ in,
                                      __half* __restrict__ out, int R, int C)
{
    __shared__ float tile[32][33];
    int c0 = blockIdx.x * 32, r0 = blockIdx.y * 32;
    int tx = threadIdx.x, ty = threadIdx.y;
#pragma unroll
    for (int i = 0; i < 32; i += 8)
        tile[ty + i][tx] = in[(size_t)(r0 + ty + i) * C + c0 + tx];
    __syncthreads();
#pragma unroll
    for (int i = 0; i < 32; i += 8)
        out[(size_t)(c0 + ty + i) * R + r0 + tx] = __float2half(tile[tx][ty + i]);
}

__global__ void rope_table_kernel()
{
    int idx = blockIdx.x * blockDim.x + threadIdx.x;
    if (idx >= S_LEN * 64) return;
    int i = idx & 63;
    int s = idx >> 6;
    double invf_d = pow(10000.0, -(double)(2 * i) / 128.0);
    float invf_f  = (float)invf_d;
    float ang_f   = (float)s * invf_f;
    double ds, dc;
    sincos((double)ang_f, &ds, &dc);
    g_cos[idx] = (float)dc;
    g_sin[idx] = (float)ds;
}

// ---------------------------------------------------------------------------
// fp16 GEMM: C[M,N] = A[M,K] @ Bt^T (+bias, +optional fused rope on q/k).
// Block 128x256x32, 8 warps (4Mx2N), warp tile 32x128 (= exactly one head:
// rotate-half partner of fragment nf<8 is fragment nf+8 in the SAME thread).
// 3-stage cp.async, dynamic smem 92160 B. Smem rows: 16 data + 4 pad words.
// ---------------------------------------------------------------------------
#define GW 20
#define ASTG (128 * GW)          // words per A stage
#define BSTG (256 * GW)          // words per B stage
#define GEMM_SMEM_BYTES (3 * (ASTG + BSTG) * 4)   // 92160

template <bool HAS_BIAS, bool DO_ROPE, typename OutT>
__global__ __launch_bounds__(256) void gemm_fp16_kernel(
    const __half* __restrict__ A, const __half* __restrict__ Bt,
    const float* __restrict__ bias, OutT* __restrict__ C,
    int M, int N, int K)
{
    extern __shared__ __align__(16) uint32_t dsm[];
    uint32_t* Asb = dsm;               // 3 stages
    uint32_t* Bsb = dsm + 3 * ASTG;    // 3 stages

    const int tid  = threadIdx.x;
    const int warp = tid >> 5;
    const int lane = tid & 31;
    const int wm = (warp >> 1) * 32;
    const int wn = (warp & 1) * 128;
    const int m0 = blockIdx.y * 128;
    const int n0 = blockIdx.x * 256;

    const int l8  = lane & 7, sel = lane >> 3;
    const int a_row = l8 + ((sel & 1) << 3), a_col = (sel >> 1) << 2;  // A-type
    const int b_row = l8 + ((sel >> 1) << 3), b_col = (sel & 1) << 2;  // B-type

    float acc[2][16][4];
#pragma unroll
    for (int i = 0; i < 2; i++)
#pragma unroll
        for (int j = 0; j < 16; j++)
#pragma unroll
            for (int c = 0; c < 4; c++) acc[i][j][c] = 0.f;

    const int arow = tid >> 1;          // A: 2 threads/row, 2 chunks each
    const int ach  = (tid & 1) * 2;

    auto load_stage = [&](int st, int kb) {
        uint32_t* As = Asb + st * ASTG;
        uint32_t* Bs = Bsb + st * BSTG;
#pragma unroll
        for (int j = 0; j < 2; j++) {
            int ch = ach + j;
            cpa16u(smem_u32(&As[arow * GW + ch * 4]),
                   A + (size_t)(m0 + arow) * K + kb + ch * 8);
        }
#pragma unroll
        for (int j = 0; j < 4; j++) {   // B: 1 thread/row (256 rows), 4 chunks
            cpa16u(smem_u32(&Bs[tid * GW + j * 4]),
                   Bt + (size_t)(n0 + tid) * K + kb + j * 8);
        }
        asm volatile("cp.async.commit_group;\n" ::);
    };

    const int nk = K / 32;
    load_stage(0, 0);
    load_stage(1, 32);

    for (int t = 0; t < nk; t++) {
        if (t + 2 < nk) asm volatile("cp.async.wait_group 1;\n" ::);
        else            asm volatile("cp.async.wait_group 0;\n" ::);
        __syncthreads();
        if (t + 2 < nk) load_stage((t + 2) % 3, (t + 2) * 32);

        const uint32_t* Asm = Asb + (t % 3) * ASTG;
        const uint32_t* Bsm = Bsb + (t % 3) * BSTG;

#pragma unroll
        for (int step = 0; step < 2; step++) {
            uint32_t a[2][4];
#pragma unroll
            for (int mf = 0; mf < 2; mf++)
                ldsm_x4(a[mf], smem_u32(&Asm[(wm + mf * 16 + a_row) * GW + step * 8 + a_col]));
#pragma unroll
            for (int nfp = 0; nfp < 8; nfp++) {
                uint32_t b[4];
                ldsm_x4(b, smem_u32(&Bsm[(wn + nfp * 16 + b_row) * GW + step * 8 + b_col]));
                mma_fp16(acc[0][2 * nfp],     a[0], b);
                mma_fp16(acc[1][2 * nfp],     a[1], b);
                mma_fp16(acc[0][2 * nfp + 1], a[0], b + 2);
                mma_fp16(acc[1][2 * nfp + 1], a[1], b + 2);
            }
        }
    }

    const int lr = lane >> 2, lc = lane & 3;
    const int colbase = n0 + wn;       // warp covers [colbase, colbase+128)

    // bias
    if (HAS_BIAS) {
#pragma unroll
        for (int nf = 0; nf < 16; nf++) {
            float b0 = bias[colbase + nf * 8 + 2 * lc];
            float b1 = bias[colbase + nf * 8 + 2 * lc + 1];
#pragma unroll
            for (int mf = 0; mf < 2; mf++) {
                acc[mf][nf][0] += b0; acc[mf][nf][1] += b1;
                acc[mf][nf][2] += b0; acc[mf][nf][3] += b1;
            }
        }
    }

    // fused rope (q,k region only): partner of nf is nf+8, same thread
    if (DO_ROPE && colbase < 2 * HID) {
#pragma unroll
        for (int mf = 0; mf < 2; mf++) {
            int rbase = m0 + wm + mf * 16 + lr;
#pragma unroll
            for (int nf = 0; nf < 8; nf++) {
#pragma unroll
                for (int c = 0; c < 4; c++) {
                    int s = rbase + ((c >> 1) << 3);        // row
                    int j = nf * 8 + 2 * lc + (c & 1);      // 0..63
                    float cs = g_cos[s * 64 + j];
                    float sn = g_sin[s * 64 + j];
                    float lo = acc[mf][nf][c];
                    float hi = acc[mf][nf + 8][c];
                    acc[mf][nf][c]     = lo * cs - hi * sn;
                    acc[mf][nf + 8][c] = hi * cs + lo * sn;
                }
            }
        }
    }

#pragma unroll
    for (int mf = 0; mf < 2; mf++)
#pragma unroll
        for (int nf = 0; nf < 16; nf++) {
            int r0i = m0 + wm + mf * 16 + lr;
            int col = colbase + nf * 8 + 2 * lc;
            if (sizeof(OutT) == 2) {
                *(__half2*)((__half*)C + (size_t)r0i * N + col) =
                    __floats2half2_rn(acc[mf][nf][0], acc[mf][nf][1]);
                *(__half2*)((__half*)C + (size_t)(r0i + 8) * N + col) =
                    __floats2half2_rn(acc[mf][nf][2], acc[mf][nf][3]);
            } else {
                float* c0p = (float*)C + (size_t)r0i * N + col;
                float* c1p = (float*)C + (size_t)(r0i + 8) * N + col;
                c0p[0] = acc[mf][nf][0]; c0p[1] = acc[mf][nf][1];
                c1p[0] = acc[mf][nf][2]; c1p[1] = acc[mf][nf][3];
            }
        }
}

// ---------------------------------------------------------------------------
// fp16 flash attention, causal (UNCHANGED from round 10 — validated).
// ---------------------------------------------------------------------------
#define KW 68
#define PW 20

__global__ __launch_bounds__(256) void flash_fp16_kernel(
    const __half* __restrict__ qkv, __half* __restrict__ ctx)
{
    __shared__ __align__(16) uint32_t Ks[2][32 * KW];
    __shared__ __align__(16) uint32_t Vs[2][32 * KW];
    __shared__ __align__(16) uint32_t Ps[8 * 16 * PW];

    const int tid  = threadIdx.x;
    const int warp = tid >> 5;
    const int lane = tid & 31;
    const int lr = lane >> 2;
    const int lc = lane & 3;
    const int qt = 15 - blockIdx.x;
    const int h  = blockIdx.y;
    const int q0 = qt * 128;
    const float scale = 0.08838834764831845f;

    const int l8  = lane & 7, sel = lane >> 3;
    const int a_row = l8 + ((sel & 1) << 3), a_col = (sel >> 1) << 2;
    const int b_row = l8 + ((sel >> 1) << 3), b_col = (sel & 1) << 2;

    uint32_t qa[8][4];
    {
        const __half* Qb = qkv + (size_t)(q0 + warp * 16) * QKV_N + h * HDIM;
#pragma unroll
        for (int st = 0; st < 8; st++) {
            qa[st][0] = *(const uint32_t*)(Qb + (size_t)lr       * QKV_N + st * 16 + 2 * lc);
            qa[st][1] = *(const uint32_t*)(Qb + (size_t)(lr + 8) * QKV_N + st * 16 + 2 * lc);
            qa[st][2] = *(const uint32_t*)(Qb + (size_t)lr       * QKV_N + st * 16 + 2 * lc + 8);
            qa[st][3] = *(const uint32_t*)(Qb + (size_t)(lr + 8) * QKV_N + st * 16 + 2 * lc + 8);
        }
    }

    float o[16][4];
#pragma unroll
    for (int i = 0; i < 16; i++)
#pragma unroll
        for (int c = 0; c < 4; c++) o[i][c] = 0.f;
    float mA = -1e30f, mB = -1e30f, lA = 0.f, lB = 0.f;

    const int rowA = q0 + warp * 16 + lr;
    const int rowB = rowA + 8;
    const int rowMaxWarp = q0 + warp * 16 + 15;
    const int ntiles = qt * 4 + 4;

    auto load_tile = [&](int st, int jt) {
#pragma unroll
        for (int it = 0; it < 2; it++) {
            int id  = tid + it * 256;
            int key = id >> 4;
            int ch  = id & 15;
            const __half* Kg = qkv + (size_t)(jt * 32 + key) * QKV_N + HID + h * HDIM + ch * 8;
            cpa16u(smem_u32(&Ks[st][key * KW + ch * 4]), Kg);
            cpa16u(smem_u32(&Vs[st][key * KW + ch * 4]), Kg + HID);
        }
        asm volatile("cp.async.commit_group;\n" ::);
    };

    load_tile(0, 0);

    for (int j = 0; j < ntiles; j++) {
        asm volatile("cp.async.wait_group 0;\n" ::);
        __syncthreads();
        if (j + 1 < ntiles) load_tile((j + 1) & 1, j + 1);

        const uint32_t* Ksm = Ks[j & 1];
        const uint32_t* Vsm = Vs[j & 1];
        const bool active = (j * 32 <= rowMaxWarp);
        if (active) {
            float s[4][4];
#pragma unroll
            for (int nf = 0; nf < 4; nf++)
#pragma unroll
                for (int c = 0; c < 4; c++) s[nf][c] = 0.f;
#pragma unroll
            for (int st = 0; st < 8; st++) {
#pragma unroll
                for (int nfp = 0; nfp < 2; nfp++) {
                    uint32_t b[4];
                    ldsm_x4(b, smem_u32(&Ksm[(nfp * 16 + b_row) * KW + st * 8 + b_col]));
                    mma_fp16(s[2 * nfp],     qa[st], b);
                    mma_fp16(s[2 * nfp + 1], qa[st], b + 2);
                }
            }

#pragma unroll
            for (int nf = 0; nf < 4; nf++) {
                int col0 = j * 32 + nf * 8 + 2 * lc;
                s[nf][0] = (col0     > rowA) ? -1e30f : s[nf][0] * scale;
                s[nf][1] = (col0 + 1 > rowA) ? -1e30f : s[nf][1] * scale;
                s[nf][2] = (col0     > rowB) ? -1e30f : s[nf][2] * scale;
                s[nf][3] = (col0 + 1 > rowB) ? -1e30f : s[nf][3] * scale;
            }

            float tA = -1e30f, tB = -1e30f;
#pragma unroll
            for (int nf = 0; nf < 4; nf++) {
                tA = fmaxf(tA, fmaxf(s[nf][0], s[nf][1]));
                tB = fmaxf(tB, fmaxf(s[nf][2], s[nf][3]));
            }
            tA = fmaxf(tA, __shfl_xor_sync(0xffffffffu, tA, 1));
            tA = fmaxf(tA, __shfl_xor_sync(0xffffffffu, tA, 2));
            tB = fmaxf(tB, __shfl_xor_sync(0xffffffffu, tB, 1));
            tB = fmaxf(tB, __shfl_xor_sync(0xffffffffu, tB, 2));

            float mAn = fmaxf(mA, tA), mBn = fmaxf(mB, tB);
            float aA = __expf(mA - mAn), aB = __expf(mB - mBn);
            float sA = 0.f, sB = 0.f;
#pragma unroll
            for (int nf = 0; nf < 4; nf++) {
                s[nf][0] = __expf(s[nf][0] - mAn);
                s[nf][1] = __expf(s[nf][1] - mAn);
                s[nf][2] = __expf(s[nf][2] - mBn);
                s[nf][3] = __expf(s[nf][3] - mBn);
                sA += s[nf][0] + s[nf][1];
                sB += s[nf][2] + s[nf][3];
            }
            sA += __shfl_xor_sync(0xffffffffu, sA, 1);
            sA += __shfl_xor_sync(0xffffffffu, sA, 2);
            sB += __shfl_xor_sync(0xffffffffu, sB, 1);
            sB += __shfl_xor_sync(0xffffffffu, sB, 2);
            lA = lA * aA + sA;
            lB = lB * aB + sB;
            mA = mAn; mB = mBn;
#pragma unroll
            for (int nf = 0; nf < 16; nf++) {
                o[nf][0] *= aA; o[nf][1] *= aA;
                o[nf][2] *= aB; o[nf][3] *= aB;
            }

            uint32_t* P = Ps + warp * 16 * PW;
#pragma unroll
            for (int nf = 0; nf < 4; nf++) {
                P[lr       * PW + nf * 4 + lc] = pack_h2(s[nf][0], s[nf][1]);
                P[(lr + 8) * PW + nf * 4 + lc] = pack_h2(s[nf][2], s[nf][3]);
            }
            __syncwarp();

#pragma unroll
            for (int st = 0; st < 2; st++) {
                uint32_t pa[4];
                ldsm_x4(pa, smem_u32(&P[a_row * PW + st * 8 + a_col]));
#pragma unroll
                for (int nfp = 0; nfp < 8; nfp++) {
                    uint32_t b[4];
                    ldsm_x4_t(b, smem_u32(&Vsm[(st * 16 + a_row) * KW + nfp * 8 + a_col]));
                    mma_fp16(o[2 * nfp],     pa, b);
                    mma_fp16(o[2 * nfp + 1], pa, b + 2);
                }
            }
        }
    }

    float rA = 1.f / lA, rB = 1.f / lB;
#pragma unroll
    for (int nf = 0; nf < 16; nf++) {
        int col = h * HDIM + nf * 8 + 2 * lc;
        *(__half2*)(ctx + (size_t)rowA * HID + col) =
            __floats2half2_rn(o[nf][0] * rA, o[nf][1] * rA);
        *(__half2*)(ctx + (size_t)rowB * HID + col) =
            __floats2half2_rn(o[nf][2] * rB, o[nf][3] * rB);
    }
}

// ---------------------------------------------------------------------------
// launcher
// ---------------------------------------------------------------------------
extern "C" void kernel_launch(void* const* d_in, const int* in_sizes, int n_in,
                              void* d_out, int out_size)
{
    const float* hidden = nullptr;
    const float* w_qkv  = nullptr;
    const float* b_qkv  = nullptr;
    const float* w_proj = nullptr;
    for (int i = 0; i < n_in; i++) {
        long sz = in_sizes[i];
        const float* p = (const float*)d_in[i];
        if (sz == (long)HID * QKV_N)      w_qkv = p;
        else if (sz == (long)QKV_N)       b_qkv = p;
        else {
            if (!hidden) hidden = p; else w_proj = p;
        }
    }
    float* out = (float*)d_out;

    __half *qkv_h, *ctx_h, *hid_h, *w1t, *w2t;
    cudaGetSymbolAddress((void**)&qkv_h, g_qkv_h);
    cudaGetSymbolAddress((void**)&ctx_h, g_ctx_h);
    cudaGetSymbolAddress((void**)&hid_h, g_hid_h);
    cudaGetSymbolAddress((void**)&w1t,   g_w1t_h);
    cudaGetSymbolAddress((void**)&w2t,   g_w2t_h);

    cudaFuncSetAttribute((const void*)gemm_fp16_kernel<true, true, __half>,
                         cudaFuncAttributeMaxDynamicSharedMemorySize, GEMM_SMEM_BYTES);
    cudaFuncSetAttribute((const void*)gemm_fp16_kernel<false, false, float>,
                         cudaFuncAttributeMaxDynamicSharedMemorySize, GEMM_SMEM_BYTES);

    rope_table_kernel<<<(S_LEN * 64) / 256, 256>>>();
    convert_half_kernel<<<(S_LEN * HID / 4) / 256, 256>>>(hidden, hid_h, S_LEN * HID / 4);
    transpose_half_kernel<<<dim3(QKV_N / 32, HID / 32), dim3(32, 8)>>>(w_qkv, w1t, HID, QKV_N);
    transpose_half_kernel<<<dim3(HID / 32, HID / 32), dim3(32, 8)>>>(w_proj, w2t, HID, HID);

    // qkv = hidden @ w_qkv + b, with rope fused into the epilogue
    gemm_fp16_kernel<true, true, __half>
        <<<dim3(QKV_N / 256, S_LEN / 128), 256, GEMM_SMEM_BYTES>>>(
        hid_h, w1t, b_qkv, qkv_h, S_LEN, QKV_N, HID);
    // attention
    flash_fp16_kernel<<<dim3(S_LEN / 128, NHEAD), 256>>>(qkv_h, ctx_h);
    // out = ctx @ w_proj
    gemm_fp16_kernel<false, false, float>
        <<<dim3(HID / 256, S_LEN / 128), 256, GEMM_SMEM_BYTES>>>(
        ctx_h, w2t, nullptr, out, S_LEN, HID, HID);
}